// round 16
// baseline (speedup 1.0000x reference)
#include <cuda_runtime.h>
#include <cstdint>

typedef unsigned long long ull;

#define NB 128
#define NT 256
#define BZ 32
#define TT 2048
#define FF 128
#define HH 256
#define SLOT (BZ*HH)
#define MEMOFF ((TT+1)*SLOT)

// shared memory float offsets (pair-packed)
#define O_WA 0                      // WA2[384][4 ull] : q-pairs (u0,u1), q=0:i 1:f 2:o 3:g
#define O_WP 3072                   // WP2[256][2 ull] : p-pairs (u0,u1), p=0:ci 1:cf
#define O_WO 4096                   // WO2[256][1 ull] : (Wco u0, Wco u1)
#define O_BA 4608                   // ba2[4 ull]
#define O_BP 4616                   // bp2[2 ull]
#define O_BO 4620                   // bo2[1 ull] (pad)
#define O_PA 4624                   // PA2[8][4][32] ull  (2048 fl)
#define O_PP 6672                   // PP2[8][2][32] ull  (1024 fl)
#define O_PO 7696                   // PO2[8][32] ull     (512 fl)
#define O_YA 8208                   // yA2[4][32] ull     (256 fl)
#define O_YP 8464                   // yP2[2][32] ull     (128 fl)
#define O_OP 8592                   // o preact [64]
#define O_CN 8656                   // own c_new [64]
#define SMF  8720
#define SMB  (SMF*4)

// duplicated transposed mirrors: each ull = (v,v)
__device__ ull xT2g[(long)TT*FF*BZ];    // [t][f][b]
__device__ ull hT2g[2][HH*BZ];          // [parity][u][b]
__device__ ull cT2g[2][HH*BZ];
__device__ unsigned g_bar[64];          // [0]=c counter, [32]=h counter

__device__ __forceinline__ float sgm(float v){ return 1.f/(1.f+expf(-v)); }

__device__ __forceinline__ ull pk(float lo, float hi){
  ull r; asm("mov.b64 %0, {%1,%2};" : "=l"(r) : "f"(lo), "f"(hi)); return r;
}
#define FMA2(d,a,b) asm("fma.rn.f32x2 %0, %1, %2, %0;" : "+l"(d) : "l"(a), "l"(b))
#define ADD2(d,a)   asm("add.rn.f32x2 %0, %0, %1;" : "+l"(d) : "l"(a))
#define ULL(off) (*(ull*)&sm[off])

__device__ __forceinline__ void farrive(unsigned* c){
  __syncthreads();
  if (threadIdx.x==0)
    asm volatile("red.release.gpu.global.add.u32 [%0], 1;" :: "l"(c) : "memory");
}
__device__ __forceinline__ void fwait(unsigned* c, unsigned tgt){
  if (threadIdx.x==0){
    unsigned v;
    do { asm volatile("ld.acquire.gpu.u32 %0,[%1];" : "=r"(v) : "l"(c) : "memory"); } while (v < tgt);
  }
  __syncthreads();
}

__global__ void zk(float* __restrict__ out){
  int i = blockIdx.x*blockDim.x + threadIdx.x;
  if (i < 64) g_bar[i] = 0u;
  if (i < SLOT){
    out[i]=0.f; out[MEMOFF+i]=0.f;
    hT2g[0][i]=0ull; cT2g[0][i]=0ull;
  }
}

// x transpose+dup: x[b][t][f] -> xT2[t][f][b] = (v,v)
__global__ void tk(const float* __restrict__ x){
  __shared__ float tile[BZ][FF+1];
  int t = blockIdx.x;
  for (int idx=threadIdx.x; idx<BZ*FF; idx+=NT){
    int b=idx>>7, f=idx&127;
    tile[b][f] = x[((long)b*TT+t)*FF+f];
  }
  __syncthreads();
  for (int idx=threadIdx.x; idx<BZ*FF; idx+=NT){
    int f=idx>>5, b=idx&31;
    float v = tile[b][f];
    xT2g[((long)t*FF+f)*BZ+b] = pk(v,v);
  }
}

// x-part of phase A: 16 k per warp, 4 pair-accumulators
__device__ __forceinline__ void xpart(const float* sm, int s, int warp, int lane, ull* a){
  a[0]=0ull; a[1]=0ull; a[2]=0ull; a[3]=0ull;
  #pragma unroll
  for (int kk=0;kk<16;kk++){
    int k = warp*16 + kk;
    ull sv2 = xT2g[((long)s*FF + k)*BZ + lane];
    const ull* wr = (const ull*)&sm[O_WA + k*8];
    FMA2(a[0], wr[0], sv2); FMA2(a[1], wr[1], sv2);
    FMA2(a[2], wr[2], sv2); FMA2(a[3], wr[3], sv2);
  }
}

__global__ void __launch_bounds__(NT,1) lstm(
  const float* __restrict__ x,  const float* __restrict__ Wx,  const float* __restrict__ bx,
  const float* __restrict__ Wh, const float* __restrict__ bh,
  const float* __restrict__ Wci,const float* __restrict__ bci,
  const float* __restrict__ Wcf,const float* __restrict__ bcf,
  const float* __restrict__ Wco,const float* __restrict__ bco,
  float* __restrict__ out)
{
  extern __shared__ float sm[];
  const int tid=threadIdx.x, warp=tid>>5, lane=tid&31;
  const int j0 = blockIdx.x*2;

  // ---- one-time weight staging (pair-packed) ----
  for (int i=tid; i<384*4; i+=NT){
    int k=i>>2, q=i&3;
    int g0=q*HH+j0, g1=q*HH+j0+1;
    float lo = (k<FF)? Wx[g0*FF+k] : Wh[g0*HH+k-FF];
    float hi = (k<FF)? Wx[g1*FF+k] : Wh[g1*HH+k-FF];
    ULL(O_WA + i*2) = pk(lo,hi);
  }
  for (int i=tid; i<256*2; i+=NT){
    int k=i>>1, p=i&1;
    const float* W = p ? Wcf : Wci;
    ULL(O_WP + i*2) = pk(W[j0*HH+k], W[(j0+1)*HH+k]);
  }
  for (int k=tid; k<256; k+=NT)
    ULL(O_WO + k*2) = pk(Wco[j0*HH+k], Wco[(j0+1)*HH+k]);
  if (tid<4){
    int q=tid, g0=q*HH+j0, g1=q*HH+j0+1;
    ULL(O_BA + tid*2) = pk(bx[g0]+bh[g0], bx[g1]+bh[g1]);
  } else if (tid<6){
    int p=tid-4; const float* B = p ? bcf : bci;
    ULL(O_BP + p*2) = pk(B[j0], B[j0+1]);
  } else if (tid==6){
    ULL(O_BO) = pk(bco[j0], bco[j0+1]);
  }
  __syncthreads();

  float* hid = out;
  float* mem = out + MEMOFF;

  ull xa[4];
  xpart(sm, 0, warp, lane, xa);

  for (int s=0; s<TT; s++){
    const int par = s&1, nxt = par^1;
    const ull* __restrict__ cOld2 = cT2g[par];
    ull*       __restrict__ cNew2 = cT2g[nxt];
    const ull* __restrict__ hOld2 = hT2g[par];
    ull*       __restrict__ hNew2 = hT2g[nxt];

    // ---- pre-h-wait: c(s)-dependent peephole partials (published one barrier ago) ----
    float co_own = 0.f;
    if (tid<64) co_own = ((const float*)cOld2)[((j0+(tid>>5))*BZ + lane)*2];
    {
      ull p0=0ull, p1=0ull;
      #pragma unroll
      for (int kk=0;kk<32;kk++){
        int k = warp*32 + kk;
        ull c2 = cOld2[(long)k*BZ + lane];
        const ull* wp = (const ull*)&sm[O_WP + k*4];
        FMA2(p0, wp[0], c2); FMA2(p1, wp[1], c2);
      }
      ULL(O_PP + (warp*64 + lane)*2)      = p0;
      ULL(O_PP + (warp*64 + 32 + lane)*2) = p1;
    }

    if (s>0) fwait(&g_bar[32], (unsigned)s*NB);   // all h(s) mirrors visible

    // ---- h-part of phase A: 32 k per warp, FMA2 into xa ----
    {
      #pragma unroll
      for (int kk=0;kk<32;kk++){
        int k = FF + warp*32 + kk;
        ull sv2 = hOld2[(long)(warp*32+kk)*BZ + lane];
        const ull* wr = (const ull*)&sm[O_WA + k*8];
        FMA2(xa[0], wr[0], sv2); FMA2(xa[1], wr[1], sv2);
        FMA2(xa[2], wr[2], sv2); FMA2(xa[3], wr[3], sv2);
      }
    }
    #pragma unroll
    for (int q=0;q<4;q++) ULL(O_PA + (warp*128 + q*32 + lane)*2) = xa[q];
    __syncthreads();

    // ---- cross-warp reduce (pairs, ADD2) ----
    if (tid < 128){
      int q = tid>>5, b = tid&31;
      ull v = ULL(O_BA + q*2);
      #pragma unroll
      for (int w=0;w<8;w++) ADD2(v, ULL(O_PA + (w*128 + q*32 + b)*2));
      ULL(O_YA + (q*32 + b)*2) = v;
    } else if (tid < 192){
      int t2 = tid-128, p = t2>>5, b = t2&31;
      ull v = ULL(O_BP + p*2);
      #pragma unroll
      for (int w=0;w<8;w++) ADD2(v, ULL(O_PP + (w*64 + p*32 + b)*2));
      ULL(O_YP + (p*32 + b)*2) = v;
    }
    __syncthreads();

    // ---- gates, c_new (read scalar halves: +u) ----
    if (tid<64){
      int u=tid>>5, b=lane;
      float yi = sm[O_YA + (0*32+b)*2 + u] + sm[O_YP + (0*32+b)*2 + u];
      float yf = sm[O_YA + (1*32+b)*2 + u] + sm[O_YP + (1*32+b)*2 + u];
      float yo = sm[O_YA + (2*32+b)*2 + u];
      float yg = sm[O_YA + (3*32+b)*2 + u];
      float cn = sgm(yf)*co_own + sgm(yi)*tanhf(yg);
      mem[(long)(s+1)*SLOT + b*HH + j0+u] = cn;
      cNew2[(j0+u)*BZ + b] = pk(cn,cn);
      sm[O_OP + tid] = yo;
      sm[O_CN + tid] = cn;
    }
    farrive(&g_bar[0]);

    // ---- hidden under c-wait: next step's x-part ----
    if (s+1<TT) xpart(sm, s+1, warp, lane, xa);

    fwait(&g_bar[0], (unsigned)(s+1)*NB);      // all c_new mirrors visible

    // ---- phase B: o-peephole from cNew (pairs) ----
    {
      ull ao = 0ull;
      #pragma unroll
      for (int kk=0;kk<32;kk++){
        int k = warp*32 + kk;
        ull c2 = cNew2[(long)k*BZ + lane];
        FMA2(ao, ULL(O_WO + k*2), c2);
      }
      ULL(O_PO + (warp*32 + lane)*2) = ao;
    }
    __syncthreads();
    if (tid<64){
      int u=tid>>5, b=lane;
      float v = sm[O_BO + u] + sm[O_OP + tid];
      #pragma unroll
      for (int w=0;w<8;w++) v += sm[O_PO + (w*32 + b)*2 + u];
      float oo = sgm(v);
      float cn = sm[O_CN + tid];
      float hn = oo*tanhf(cn);
      hid[(long)(s+1)*SLOT + b*HH + j0+u] = hn;
      hNew2[(j0+u)*BZ + b] = pk(hn,hn);
    }
    farrive(&g_bar[32]);
    // h-wait at top of next step
  }
}

extern "C" void kernel_launch(void* const* d_in, const int* in_sizes, int n_in,
                              void* d_out, int out_size) {
  cudaFuncSetAttribute(lstm, cudaFuncAttributeMaxDynamicSharedMemorySize, SMB);
  float* out = (float*)d_out;
  const float* xin = (const float*)d_in[0];
  zk<<<32, 256>>>(out);
  tk<<<TT, NT>>>(xin);
  lstm<<<NB, NT, SMB>>>(
    xin, (const float*)d_in[1], (const float*)d_in[2],
    (const float*)d_in[3], (const float*)d_in[4],
    (const float*)d_in[5], (const float*)d_in[6],
    (const float*)d_in[7], (const float*)d_in[8],
    (const float*)d_in[9], (const float*)d_in[10],
    out);
}

// round 17
// speedup vs baseline: 1.0484x; 1.0484x over previous
#include <cuda_runtime.h>
#include <cstdint>

#define NB 128
#define NT 256
#define BZ 32
#define TT 2048
#define FF 128
#define HH 256
#define SLOT (BZ*HH)
#define MEMOFF ((TT+1)*SLOT)

// shared memory float offsets
#define O_WA 0                      // WA[384][8]   r=u*4+q (k<128 x, else h)
#define O_WP (O_WA+384*8)           // WP[256][4]   r=u*2+p
#define O_WO (O_WP+256*4)           // WO[256][2]
#define O_BA (O_WO+256*2)           // ba[8]
#define O_BP (O_BA+8)               // bp[4]
#define O_BO (O_BP+4)               // bo[4]
#define O_PA (O_BO+4)               // PA[8][8][32]
#define O_PP (O_PA+2048)            // PP[8][4][32]
#define O_PO (O_PP+1024)            // PO[8][2][32]
#define O_YA (O_PO+512)             // yA[8][32]
#define O_YP (O_YA+256)             // yP[4][32]
#define O_OP (O_YP+128)             // o preact [64]
#define O_CC (O_OP+64)              // c cache [256][32]  (current c, full vector)
#define SMF  (O_CC+8192)
#define SMB  (SMF*4)

// transposed state mirrors (batch-minor)
__device__ float xTg[(long)TT*FF*BZ];   // [t][f][b]
__device__ float hTg[2][HH*BZ];         // [parity][u][b]
__device__ float cTg[2][HH*BZ];
__device__ unsigned g_bar[64];          // [0]=c counter, [32]=h counter

__device__ __forceinline__ float sgm(float v){ return 1.f/(1.f+expf(-v)); }

__device__ __forceinline__ void farrive(unsigned* c){
  __syncthreads();
  if (threadIdx.x==0)
    asm volatile("red.release.gpu.global.add.u32 [%0], 1;" :: "l"(c) : "memory");
}
__device__ __forceinline__ void fwait(unsigned* c, unsigned tgt){
  if (threadIdx.x==0){
    unsigned v;
    do { asm volatile("ld.acquire.gpu.u32 %0,[%1];" : "=r"(v) : "l"(c) : "memory"); } while (v < tgt);
  }
  __syncthreads();
}

__global__ void zk(float* __restrict__ out){
  int i = blockIdx.x*blockDim.x + threadIdx.x;
  if (i < 64) g_bar[i] = 0u;
  if (i < SLOT){
    out[i]=0.f; out[MEMOFF+i]=0.f;
    hTg[0][i]=0.f;                       // h0 = 0 mirror
  }
}

// x transpose: x[b][t][f] -> xT[t][f][b]
__global__ void tk(const float* __restrict__ x){
  __shared__ float tile[BZ][FF+1];
  int t = blockIdx.x;
  for (int idx=threadIdx.x; idx<BZ*FF; idx+=NT){
    int b=idx>>7, f=idx&127;
    tile[b][f] = x[((long)b*TT+t)*FF+f];
  }
  __syncthreads();
  for (int idx=threadIdx.x; idx<BZ*FF; idx+=NT){
    int f=idx>>5, b=idx&31;
    xTg[((long)t*FF+f)*BZ+b] = tile[b][f];
  }
}

// x-part of phase A: 16 k per warp, accumulate 8 gate rows
__device__ __forceinline__ void xpart(const float* sm, int s, int warp, int lane, float* a){
  #pragma unroll
  for (int r=0;r<8;r++) a[r]=0.f;
  float sv[16];
  #pragma unroll
  for (int kk=0;kk<16;kk++)
    sv[kk] = xTg[((long)s*FF + warp*16 + kk)*BZ + lane];
  #pragma unroll
  for (int kk=0;kk<16;kk++){
    int k = warp*16 + kk;
    float4 w0 = *(float4*)&sm[O_WA + k*8];
    float4 w1 = *(float4*)&sm[O_WA + k*8+4];
    a[0]+=w0.x*sv[kk]; a[1]+=w0.y*sv[kk]; a[2]+=w0.z*sv[kk]; a[3]+=w0.w*sv[kk];
    a[4]+=w1.x*sv[kk]; a[5]+=w1.y*sv[kk]; a[6]+=w1.z*sv[kk]; a[7]+=w1.w*sv[kk];
  }
}

__global__ void __launch_bounds__(NT,1) lstm(
  const float* __restrict__ x,  const float* __restrict__ Wx,  const float* __restrict__ bx,
  const float* __restrict__ Wh, const float* __restrict__ bh,
  const float* __restrict__ Wci,const float* __restrict__ bci,
  const float* __restrict__ Wcf,const float* __restrict__ bcf,
  const float* __restrict__ Wco,const float* __restrict__ bco,
  float* __restrict__ out)
{
  extern __shared__ float sm[];
  const int tid=threadIdx.x, warp=tid>>5, lane=tid&31;
  const int j0 = blockIdx.x*2;

  // ---- one-time weight staging ----
  for (int i=tid; i<384*8; i+=NT){
    int k=i>>3, r=i&7, u=r>>2, q=r&3, g=q*HH+j0+u;
    sm[O_WA+i] = (k<FF) ? Wx[g*FF+k] : Wh[g*HH+k-FF];
  }
  for (int i=tid; i<256*4; i+=NT){
    int k=i>>2, r=i&3, u=r>>1, p=r&1;
    sm[O_WP+i] = (p?Wcf:Wci)[(j0+u)*HH+k];
  }
  for (int i=tid; i<256*2; i+=NT){
    int k=i>>1, u=i&1; sm[O_WO+i] = Wco[(j0+u)*HH+k];
  }
  if (tid<8){ int u=tid>>2,q=tid&3,g=q*HH+j0+u; sm[O_BA+tid]=bx[g]+bh[g]; }
  else if (tid<12){ int r=tid-8,u=r>>1; sm[O_BP+r]=((r&1)?bcf:bci)[j0+u]; }
  else if (tid<14){ sm[O_BO+tid-12]=bco[j0+tid-12]; }
  // c cache = 0 (c0 = 0)
  for (int i=tid; i<8192; i+=NT) sm[O_CC+i]=0.f;
  __syncthreads();

  float* hid = out;
  float* mem = out + MEMOFF;

  float xa[8];
  xpart(sm, 0, warp, lane, xa);

  float hn_prev = 0.f;    // deferred hid STG (tid<64)

  for (int s=0; s<TT; s++){
    const int par = s&1, nxt = par^1;
    float*       __restrict__ cNew = cTg[nxt];
    const float* __restrict__ hOld = hTg[par];
    float*       __restrict__ hNew = hTg[nxt];

    // ---- deferred hid STG from previous step (off the release path) ----
    if (s>0 && tid<64)
      hid[(long)s*SLOT + lane*HH + j0+(tid>>5)] = hn_prev;

    // ---- pre-h-wait: peephole i/f partials from smem c-cache (no L2) ----
    float cv[32];
    #pragma unroll
    for (int kk=0;kk<32;kk++) cv[kk] = sm[O_CC + (warp*32+kk)*32 + lane];
    float co_own = 0.f;
    if (tid<64) co_own = sm[O_CC + (j0+(tid>>5))*32 + lane];
    {
      float p0=0,p1=0,p2=0,p3=0;
      #pragma unroll
      for (int kk=0;kk<32;kk++){
        int k = warp*32 + kk;
        float4 w = *(float4*)&sm[O_WP + k*4];
        p0+=w.x*cv[kk]; p1+=w.y*cv[kk]; p2+=w.z*cv[kk]; p3+=w.w*cv[kk];
      }
      sm[O_PP + warp*128 + 0*32 + lane]=p0; sm[O_PP + warp*128 + 1*32 + lane]=p1;
      sm[O_PP + warp*128 + 2*32 + lane]=p2; sm[O_PP + warp*128 + 3*32 + lane]=p3;
    }

    if (s>0) fwait(&g_bar[32], (unsigned)s*NB);   // all h(s) mirrors visible

    // ---- h-part of phase A: 32 k per warp into xa ----
    {
      float sv[32];
      #pragma unroll
      for (int kk=0;kk<32;kk++)
        sv[kk] = hOld[(warp*32+kk)*BZ + lane];
      #pragma unroll
      for (int kk=0;kk<32;kk++){
        int k = FF + warp*32 + kk;
        float4 w0 = *(float4*)&sm[O_WA + k*8];
        float4 w1 = *(float4*)&sm[O_WA + k*8+4];
        xa[0]+=w0.x*sv[kk]; xa[1]+=w0.y*sv[kk]; xa[2]+=w0.z*sv[kk]; xa[3]+=w0.w*sv[kk];
        xa[4]+=w1.x*sv[kk]; xa[5]+=w1.y*sv[kk]; xa[6]+=w1.z*sv[kk]; xa[7]+=w1.w*sv[kk];
      }
    }
    #pragma unroll
    for (int r=0;r<8;r++) sm[O_PA + warp*256 + r*32 + lane] = xa[r];
    __syncthreads();

    // ---- cross-warp reduce ----
    {
      int r=tid>>5, b=lane;
      float v = sm[O_BA+r];
      #pragma unroll
      for (int w=0;w<8;w++) v += sm[O_PA + w*256 + r*32 + b];
      sm[O_YA + r*32 + b] = v;
    }
    if (tid<128){
      int r=tid>>5, b=lane;
      float v = sm[O_BP+r];
      #pragma unroll
      for (int w=0;w<8;w++) v += sm[O_PP + w*128 + r*32 + b];
      sm[O_YP + r*32 + b] = v;
    }
    __syncthreads();

    // ---- gates, c_new (mirror store only; output STG deferred) ----
    float cn = 0.f;
    if (tid<64){
      int u=tid>>5, b=lane;
      float ii = sgm (sm[O_YA+(u*4+0)*32+b] + sm[O_YP+(u*2+0)*32+b]);
      float ff = sgm (sm[O_YA+(u*4+1)*32+b] + sm[O_YP+(u*2+1)*32+b]);
      float gg = tanhf(sm[O_YA+(u*4+3)*32+b]);
      cn = ff*co_own + ii*gg;
      cNew[(j0+u)*BZ + b] = cn;
      sm[O_OP + tid] = sm[O_YA+(u*4+2)*32+b];
    }
    farrive(&g_bar[0]);

    // ---- hidden under c-wait: deferred mem STG + next step's x-part ----
    if (tid<64)
      mem[(long)(s+1)*SLOT + lane*HH + j0+(tid>>5)] = cn;
    if (s+1<TT) xpart(sm, s+1, warp, lane, xa);

    fwait(&g_bar[0], (unsigned)(s+1)*NB);      // all c_new mirrors visible

    // ---- phase B: o-peephole from cNew mirror; cache c(s+1) into smem ----
    {
      float ao0=0.f, ao1=0.f;
      float cvv[32];
      #pragma unroll
      for (int kk=0;kk<32;kk++)
        cvv[kk] = cNew[(warp*32+kk)*BZ + lane];
      #pragma unroll
      for (int kk=0;kk<32;kk++){
        int k = warp*32 + kk;
        float2 w = *(float2*)&sm[O_WO + k*2];
        ao0 += w.x*cvv[kk]; ao1 += w.y*cvv[kk];
        sm[O_CC + k*32 + lane] = cvv[kk];      // refresh c cache (next step)
      }
      sm[O_PO + warp*64 + lane]      = ao0;
      sm[O_PO + warp*64 + 32 + lane] = ao1;
    }
    __syncthreads();
    if (tid<64){
      int u=tid>>5, b=lane;
      float v = sm[O_BO+u] + sm[O_OP + tid];
      #pragma unroll
      for (int w=0;w<8;w++) v += sm[O_PO + w*64 + u*32 + b];
      float oo = sgm(v);
      float cnn = sm[O_CC + (j0+u)*32 + b];
      float hn = oo*tanhf(cnn);
      hn_prev = hn;                             // deferred hid STG
      hNew[(j0+u)*BZ + b] = hn;
    }
    farrive(&g_bar[32]);
    // h-wait at top of next step
  }

  // final deferred hid STG
  if (tid<64)
    hid[(long)TT*SLOT + lane*HH + j0+(tid>>5)] = hn_prev;
}

extern "C" void kernel_launch(void* const* d_in, const int* in_sizes, int n_in,
                              void* d_out, int out_size) {
  cudaFuncSetAttribute(lstm, cudaFuncAttributeMaxDynamicSharedMemorySize, SMB);
  float* out = (float*)d_out;
  const float* xin = (const float*)d_in[0];
  zk<<<32, 256>>>(out);
  tk<<<TT, NT>>>(xin);
  lstm<<<NB, NT, SMB>>>(
    xin, (const float*)d_in[1], (const float*)d_in[2],
    (const float*)d_in[3], (const float*)d_in[4],
    (const float*)d_in[5], (const float*)d_in[6],
    (const float*)d_in[7], (const float*)d_in[8],
    (const float*)d_in[9], (const float*)d_in[10],
    out);
}